// round 12
// baseline (speedup 1.0000x reference)
#include <cuda_runtime.h>
#include <math.h>

#define Nn 1024
#define Ff 64
#define ALPHA 0.2f

// scratch
__device__ __align__(16) float g_Wh[Nn * Ff];
__device__ float g_e1[Nn];
__device__ float g_e2[Nn];

// ---------------------------------------------------------------------------
// k1: Wh = h @ W ; e1 = Wh@a1 ; e2 = Wh@a2. grid 256 (4 rows/block),
// SMEM-staged W, 1 output/thread.
// ---------------------------------------------------------------------------
__global__ __launch_bounds__(256) void gat_k1(const float* __restrict__ h,
                                              const float* __restrict__ W,
                                              const float* __restrict__ a) {
    __shared__ float Ws[Ff * Ff];
    __shared__ float hs[4 * Ff];
    __shared__ float a1s[Ff], a2s[Ff];
    __shared__ float es1[8], es2[8];
    int t = threadIdx.x;
    int row0 = blockIdx.x * 4;

#pragma unroll
    for (int k = 0; k < 4; k++)
        ((float4*)Ws)[t + k * 256] = ((const float4*)W)[t + k * 256];
    hs[t] = h[row0 * Ff + t];
    if (t < Ff) { a1s[t] = a[t]; a2s[t] = a[Ff + t]; }
    __syncthreads();

    int ii = t >> 6;
    int f  = t & 63;
    float acc = 0.f;
#pragma unroll
    for (int k = 0; k < Ff; k++)
        acc += hs[ii * Ff + k] * Ws[k * Ff + f];
    int row = row0 + ii;
    g_Wh[row * Ff + f] = acc;

    float p1 = acc * a1s[f];
    float p2 = acc * a2s[f];
#pragma unroll
    for (int o = 16; o; o >>= 1) {
        p1 += __shfl_xor_sync(0xffffffffu, p1, o);
        p2 += __shfl_xor_sync(0xffffffffu, p2, o);
    }
    int w = t >> 5;
    if ((t & 31) == 0) { es1[w] = p1; es2[w] = p2; }
    __syncthreads();
    if (t < 4) {
        g_e1[row0 + t] = es1[2 * t] + es1[2 * t + 1];
        g_e2[row0 + t] = es2[2 * t] + es2[2 * t + 1];
    }
}

// ---------------------------------------------------------------------------
// k2: feature-split fused attention. grid 512 = 256 rowgroups x 2 f-halves,
// 256 threads, 4 CTA/SM (one full wave). Block (rg, fh): rows rg*4..+4,
// output features fh*32..+32, ALL 1024 j -> denominators fully in-block,
// zero cross-block communication.
// adj packed to a 16-bit register mask in the PDL prologue (overlaps k1).
// p-tiles: thread t owns j=t of each 256-j tile (4 rows, dup-pair st.128),
// ping-pong buffers (1 barrier/tile). GEMM: thread (fi=t&7, jg=t>>3),
// 8 j-steps/tile, Wh LDG.128 double-buffered, fma.f32x2 accumulators.
// ---------------------------------------------------------------------------
__global__ __launch_bounds__(256, 4) void gat_k2(const int* __restrict__ adj,
                                                 float* __restrict__ out) {
    __shared__ __align__(16) float ps[2][256 * 8];   // 16KB ping-pong p tiles
    __shared__ __align__(16) float red[32 * 132];    // 16.5KB split buffer
    __shared__ float red2[128];
    __shared__ float wpart[8][4];
    __shared__ float dfin[4];

    int t = threadIdx.x;
    int b = blockIdx.x;
    int rg = b >> 1;
    int fh = b & 1;
    int r0 = rg * 4;
    int fi = t & 7;
    int jg = t >> 3;

    // ---- PDL prologue: adj -> 16-bit mask (overlaps k1) ----
    unsigned int mask = 0;
#pragma unroll
    for (int jt = 0; jt < 4; jt++) {
        const int* ac = adj + jt * 256 + t;
#pragma unroll
        for (int r = 0; r < 4; r++) {
            int a = __ldg(ac + (size_t)(r0 + r) * Nn);
            mask |= (a > 0 ? 1u : 0u) << (jt * 4 + r);
        }
    }

    asm volatile("griddepcontrol.wait;" ::: "memory");

    float e2v[4];
#pragma unroll
    for (int jt = 0; jt < 4; jt++)
        e2v[jt] = __ldg(&g_e2[jt * 256 + t]);
    float e1r0 = __ldg(&g_e1[r0 + 0]);
    float e1r1 = __ldg(&g_e1[r0 + 1]);
    float e1r2 = __ldg(&g_e1[r0 + 2]);
    float e1r3 = __ldg(&g_e1[r0 + 3]);

    float d0 = 0.f, d1 = 0.f, d2 = 0.f, d3 = 0.f;
    unsigned long long acc_lo[4] = {0ull, 0ull, 0ull, 0ull};
    unsigned long long acc_hi[4] = {0ull, 0ull, 0ull, 0ull};
    const ulonglong2* WhL = (const ulonglong2*)g_Wh;
    int fcol = fh * 8 + fi;          // ulonglong2 column within a Wh row

    // ---- p tile 0 -> ps[0] ----
    {
        float e2 = e2v[0];
        float s0 = e1r0 + e2; s0 = (s0 > 0.f) ? s0 : ALPHA * s0;
        float s1 = e1r1 + e2; s1 = (s1 > 0.f) ? s1 : ALPHA * s1;
        float s2 = e1r2 + e2; s2 = (s2 > 0.f) ? s2 : ALPHA * s2;
        float s3 = e1r3 + e2; s3 = (s3 > 0.f) ? s3 : ALPHA * s3;
        float p0 = (mask & 1u) ? __expf(s0) : 0.f;
        float p1 = (mask & 2u) ? __expf(s1) : 0.f;
        float p2 = (mask & 4u) ? __expf(s2) : 0.f;
        float p3 = (mask & 8u) ? __expf(s3) : 0.f;
        d0 += p0; d1 += p1; d2 += p2; d3 += p3;
        *(float4*)&ps[0][t * 8]     = make_float4(p0, p0, p1, p1);
        *(float4*)&ps[0][t * 8 + 4] = make_float4(p2, p2, p3, p3);
    }

    // prefetch Wh batch: tile 0, steps 0..3
    ulonglong2 whbuf[4];
#pragma unroll
    for (int kk = 0; kk < 4; kk++)
        whbuf[kk] = WhL[(size_t)(kk * 32 + jg) * 16 + fcol];
    __syncthreads();

#pragma unroll
    for (int jt = 0; jt < 4; jt++) {
        const float* psb = ps[jt & 1];

        // ---- GEMM: 8 j-steps in 2 double-buffered batches of 4 ----
#pragma unroll
        for (int kb = 0; kb < 2; kb++) {
            ulonglong2 c[4];
#pragma unroll
            for (int kk = 0; kk < 4; kk++) c[kk] = whbuf[kk];

            if (kb == 0) {
#pragma unroll
                for (int kk = 0; kk < 4; kk++)
                    whbuf[kk] = WhL[(size_t)(jt * 256 + (4 + kk) * 32 + jg) * 16 + fcol];
            } else if (jt < 3) {
#pragma unroll
                for (int kk = 0; kk < 4; kk++)
                    whbuf[kk] = WhL[(size_t)((jt + 1) * 256 + kk * 32 + jg) * 16 + fcol];
            }

#pragma unroll
            for (int kk = 0; kk < 4; kk++) {
                int j = (kb * 4 + kk) * 32 + jg;
                ulonglong2 wh = c[kk];
                ulonglong2 pA = *(const ulonglong2*)&psb[j * 8];
                ulonglong2 pB = *(const ulonglong2*)&psb[j * 8 + 4];
                asm("fma.rn.f32x2 %0,%1,%2,%0;" : "+l"(acc_lo[0]) : "l"(pA.x), "l"(wh.x));
                asm("fma.rn.f32x2 %0,%1,%2,%0;" : "+l"(acc_hi[0]) : "l"(pA.x), "l"(wh.y));
                asm("fma.rn.f32x2 %0,%1,%2,%0;" : "+l"(acc_lo[1]) : "l"(pA.y), "l"(wh.x));
                asm("fma.rn.f32x2 %0,%1,%2,%0;" : "+l"(acc_hi[1]) : "l"(pA.y), "l"(wh.y));
                asm("fma.rn.f32x2 %0,%1,%2,%0;" : "+l"(acc_lo[2]) : "l"(pB.x), "l"(wh.x));
                asm("fma.rn.f32x2 %0,%1,%2,%0;" : "+l"(acc_hi[2]) : "l"(pB.x), "l"(wh.y));
                asm("fma.rn.f32x2 %0,%1,%2,%0;" : "+l"(acc_lo[3]) : "l"(pB.y), "l"(wh.x));
                asm("fma.rn.f32x2 %0,%1,%2,%0;" : "+l"(acc_hi[3]) : "l"(pB.y), "l"(wh.y));
            }
        }

        // ---- write p tile jt+1 into the other buffer ----
        if (jt < 3) {
            float e2 = e2v[jt + 1];
            float s0 = e1r0 + e2; s0 = (s0 > 0.f) ? s0 : ALPHA * s0;
            float s1 = e1r1 + e2; s1 = (s1 > 0.f) ? s1 : ALPHA * s1;
            float s2 = e1r2 + e2; s2 = (s2 > 0.f) ? s2 : ALPHA * s2;
            float s3 = e1r3 + e2; s3 = (s3 > 0.f) ? s3 : ALPHA * s3;
            unsigned int m = mask >> ((jt + 1) * 4);
            float p0 = (m & 1u) ? __expf(s0) : 0.f;
            float p1 = (m & 2u) ? __expf(s1) : 0.f;
            float p2 = (m & 4u) ? __expf(s2) : 0.f;
            float p3 = (m & 8u) ? __expf(s3) : 0.f;
            d0 += p0; d1 += p1; d2 += p2; d3 += p3;
            *(float4*)&ps[(jt + 1) & 1][t * 8]     = make_float4(p0, p0, p1, p1);
            *(float4*)&ps[(jt + 1) & 1][t * 8 + 4] = make_float4(p2, p2, p3, p3);
        }
        __syncthreads();
    }

    // ---- dsum: warp-reduce then per-warp partials ----
#pragma unroll
    for (int o = 16; o; o >>= 1) {
        d0 += __shfl_xor_sync(0xffffffffu, d0, o);
        d1 += __shfl_xor_sync(0xffffffffu, d1, o);
        d2 += __shfl_xor_sync(0xffffffffu, d2, o);
        d3 += __shfl_xor_sync(0xffffffffu, d3, o);
    }
    if ((t & 31) == 0) {
        int w = t >> 5;
        wpart[w][0] = d0; wpart[w][1] = d1; wpart[w][2] = d2; wpart[w][3] = d3;
    }

    // ---- write register tiles to red[jg] (4 rows x 4 f each) ----
#pragma unroll
    for (int ii = 0; ii < 4; ii++) {
        float2 lo = *(float2*)&acc_lo[ii];
        float2 hi = *(float2*)&acc_hi[ii];
        *(float4*)&red[jg * 132 + ii * 32 + fi * 4] = make_float4(lo.x, lo.y, hi.x, hi.y);
    }
    __syncthreads();

    // ---- combine: 32 splits -> 2 half-sums of 16 -> combine ----
    if (t < 4) {
        float dd = 0.f;
#pragma unroll
        for (int w2 = 0; w2 < 8; w2++) dd += wpart[w2][t];
        dfin[t] = dd;
    }
    {
        int e = t & 127;                // 4 rows x 32 f
        int half = t >> 7;
        float val = 0.f;
#pragma unroll
        for (int g = 0; g < 16; g++)
            val += red[(half * 16 + g) * 132 + e];
        if (half == 1) red2[e] = val;
        __syncthreads();
        if (half == 0) {
            val += red2[e];
            int oii = e >> 5;
            int of  = e & 31;
            float r = val / dfin[oii];
            r = (r > 0.f) ? r : expm1f(r);
            out[(size_t)(r0 + oii) * Ff + fh * 32 + of] = r;
        }
    }
}

// ---------------------------------------------------------------------------
extern "C" void kernel_launch(void* const* d_in, const int* in_sizes, int n_in,
                              void* d_out, int out_size) {
    const float* h   = (const float*)d_in[0];
    const int*   adj = (const int*)d_in[1];
    const float* W   = (const float*)d_in[2];
    const float* a   = (const float*)d_in[3];
    float* out = (float*)d_out;

    gat_k1<<<256, 256>>>(h, W, a);

    cudaLaunchConfig_t cfg = {};
    cfg.gridDim  = dim3(512, 1, 1);
    cfg.blockDim = dim3(256, 1, 1);
    cfg.dynamicSmemBytes = 0;
    cfg.stream = 0;
    cudaLaunchAttribute attrs[1];
    attrs[0].id = cudaLaunchAttributeProgrammaticStreamSerialization;
    attrs[0].val.programmaticStreamSerializationAllowed = 1;
    cfg.attrs = attrs;
    cfg.numAttrs = 1;
    cudaLaunchKernelEx(&cfg, gat_k2, adj, (float*)out);
}

// round 13
// speedup vs baseline: 1.1552x; 1.1552x over previous
#include <cuda_runtime.h>
#include <math.h>

#define Nn 1024
#define Ff 64
#define ALPHA 0.2f

// scratch
__device__ __align__(16) float g_Wh[Nn * Ff];
__device__ float g_e1[Nn];
__device__ float g_e2[Nn];

// ---------------------------------------------------------------------------
// k1: Wh = h @ W ; e1 = Wh@a1 ; e2 = Wh@a2. grid 256 (4 rows/block),
// SMEM-staged W, 1 output/thread.
// ---------------------------------------------------------------------------
__global__ __launch_bounds__(256) void gat_k1(const float* __restrict__ h,
                                              const float* __restrict__ W,
                                              const float* __restrict__ a) {
    __shared__ float Ws[Ff * Ff];
    __shared__ float hs[4 * Ff];
    __shared__ float a1s[Ff], a2s[Ff];
    __shared__ float es1[8], es2[8];
    int t = threadIdx.x;
    int row0 = blockIdx.x * 4;

#pragma unroll
    for (int k = 0; k < 4; k++)
        ((float4*)Ws)[t + k * 256] = ((const float4*)W)[t + k * 256];
    hs[t] = h[row0 * Ff + t];
    if (t < Ff) { a1s[t] = a[t]; a2s[t] = a[Ff + t]; }
    __syncthreads();

    int ii = t >> 6;
    int f  = t & 63;
    float acc = 0.f;
#pragma unroll
    for (int k = 0; k < Ff; k++)
        acc += hs[ii * Ff + k] * Ws[k * Ff + f];
    int row = row0 + ii;
    g_Wh[row * Ff + f] = acc;

    float p1 = acc * a1s[f];
    float p2 = acc * a2s[f];
#pragma unroll
    for (int o = 16; o; o >>= 1) {
        p1 += __shfl_xor_sync(0xffffffffu, p1, o);
        p2 += __shfl_xor_sync(0xffffffffu, p2, o);
    }
    int w = t >> 5;
    if ((t & 31) == 0) { es1[w] = p1; es2[w] = p2; }
    __syncthreads();
    if (t < 4) {
        g_e1[row0 + t] = es1[2 * t] + es1[2 * t + 1];
        g_e2[row0 + t] = es2[2 * t] + es2[2 * t + 1];
    }
}

// ---------------------------------------------------------------------------
// k2: fused attention, out = elu( (P@Wh)/rowsum ), unnormalized softmax.
// grid 256 (4 rows/block), 512 threads (2 CTA/SM).
// ALL p-tiles (1024 j, dup-pairs, 32KB) computed up front -> the whole
// 32-step GEMM runs with ZERO barriers inside (one ILP window, no
// straggler re-syncs). red reduction buffer OVERLAYS ps (disjoint
// lifetimes). 4 barriers total (was ~10).
// PDL: adj prologue overlaps k1.
// ---------------------------------------------------------------------------
__global__ __launch_bounds__(512, 2) void gat_k2(const int* __restrict__ adj,
                                                 float* __restrict__ out) {
    __shared__ __align__(16) float sbuf[8448];  // ps[0,8192) ∪ red[0,8448)
    __shared__ float red2[256];
    __shared__ float wpart[16][2];
    __shared__ float dfin[4];

    int t = threadIdx.x;
    int r0 = blockIdx.x * 4;
    int half = t >> 8;               // 0: rows 0,1 ; 1: rows 2,3
    int jc = t & 255;
    int fi = t & 15;
    int jg = (t >> 4) & 31;

    // ---- PDL prologue: adj loads (independent of k1) ----
    int av[4][2];
#pragma unroll
    for (int jt = 0; jt < 4; jt++) {
        const int* ac = adj + jt * 256 + jc;
        av[jt][0] = __ldg(ac + (size_t)(r0 + half * 2 + 0) * Nn);
        av[jt][1] = __ldg(ac + (size_t)(r0 + half * 2 + 1) * Nn);
    }

    asm volatile("griddepcontrol.wait;" ::: "memory");

    float e2v[4];
#pragma unroll
    for (int jt = 0; jt < 4; jt++)
        e2v[jt] = __ldg(&g_e2[jt * 256 + jc]);
    float e1a = __ldg(&g_e1[r0 + half * 2 + 0]);
    float e1b = __ldg(&g_e1[r0 + half * 2 + 1]);

    // ---- ALL p-tiles up front (each thread: 2 rows x 4 tiles) ----
    float* ps = sbuf;
    float da = 0.f, db = 0.f;
#pragma unroll
    for (int jt = 0; jt < 4; jt++) {
        float e2 = e2v[jt];
        float s0 = e1a + e2; s0 = (s0 > 0.f) ? s0 : ALPHA * s0;
        float s1 = e1b + e2; s1 = (s1 > 0.f) ? s1 : ALPHA * s1;
        float p0 = (av[jt][0] > 0) ? __expf(s0) : 0.f;
        float p1 = (av[jt][1] > 0) ? __expf(s1) : 0.f;
        da += p0; db += p1;
        *(float4*)&ps[(jt * 256 + jc) * 8 + half * 4] = make_float4(p0, p0, p1, p1);
    }

    // prefetch Wh batch 0 (steps 0..3)
    const ulonglong2* WhL = (const ulonglong2*)g_Wh;
    ulonglong2 whbuf[4];
#pragma unroll
    for (int kk = 0; kk < 4; kk++)
        whbuf[kk] = WhL[(size_t)(kk * 32 + jg) * 16 + fi];

    unsigned long long acc_lo[4] = {0ull, 0ull, 0ull, 0ull};
    unsigned long long acc_hi[4] = {0ull, 0ull, 0ull, 0ull};
    __syncthreads();                       // (1) ps complete

    // ---- GEMM: 32 j-steps, NO barriers, 8 double-buffered batches ----
#pragma unroll
    for (int kb = 0; kb < 8; kb++) {
        ulonglong2 c[4];
#pragma unroll
        for (int kk = 0; kk < 4; kk++) c[kk] = whbuf[kk];

        if (kb < 7) {
#pragma unroll
            for (int kk = 0; kk < 4; kk++)
                whbuf[kk] = WhL[(size_t)(((kb + 1) * 4 + kk) * 32 + jg) * 16 + fi];
        }

#pragma unroll
        for (int kk = 0; kk < 4; kk++) {
            int j = (kb * 4 + kk) * 32 + jg;
            ulonglong2 wh = c[kk];
            ulonglong2 pA = *(const ulonglong2*)&ps[j * 8];
            ulonglong2 pB = *(const ulonglong2*)&ps[j * 8 + 4];
            asm("fma.rn.f32x2 %0,%1,%2,%0;" : "+l"(acc_lo[0]) : "l"(pA.x), "l"(wh.x));
            asm("fma.rn.f32x2 %0,%1,%2,%0;" : "+l"(acc_hi[0]) : "l"(pA.x), "l"(wh.y));
            asm("fma.rn.f32x2 %0,%1,%2,%0;" : "+l"(acc_lo[1]) : "l"(pA.y), "l"(wh.x));
            asm("fma.rn.f32x2 %0,%1,%2,%0;" : "+l"(acc_hi[1]) : "l"(pA.y), "l"(wh.y));
            asm("fma.rn.f32x2 %0,%1,%2,%0;" : "+l"(acc_lo[2]) : "l"(pB.x), "l"(wh.x));
            asm("fma.rn.f32x2 %0,%1,%2,%0;" : "+l"(acc_hi[2]) : "l"(pB.x), "l"(wh.y));
            asm("fma.rn.f32x2 %0,%1,%2,%0;" : "+l"(acc_lo[3]) : "l"(pB.y), "l"(wh.x));
            asm("fma.rn.f32x2 %0,%1,%2,%0;" : "+l"(acc_hi[3]) : "l"(pB.y), "l"(wh.y));
        }
    }

    // ---- dsum: warp-reduce (register-only) ----
#pragma unroll
    for (int o = 16; o; o >>= 1) {
        da += __shfl_xor_sync(0xffffffffu, da, o);
        db += __shfl_xor_sync(0xffffffffu, db, o);
    }
    __syncthreads();                       // (2) all ps reads done -> red may overlay
    if ((t & 31) == 0) {
        int w = t >> 5;
        wpart[w][0] = da;
        wpart[w][1] = db;
    }

    // ---- write register tiles to red (overlays ps) ----
    float* red = sbuf;
#pragma unroll
    for (int ii = 0; ii < 4; ii++) {
        float2 lo = *(float2*)&acc_lo[ii];
        float2 hi = *(float2*)&acc_hi[ii];
        *(float4*)&red[jg * 264 + ii * 64 + fi * 4] = make_float4(lo.x, lo.y, hi.x, hi.y);
    }
    __syncthreads();                       // (3) red + wpart visible

    if (t < 4) {
        int hh = t >> 1, rr = t & 1;
        float dd = 0.f;
#pragma unroll
        for (int w2 = 0; w2 < 8; w2++) dd += wpart[hh * 8 + w2][rr];
        dfin[t] = dd;
    }

    // ---- reduce 32 splits: each half sums 16, then combine ----
    {
        int e = t & 255;
        float val = 0.f;
#pragma unroll
        for (int g = 0; g < 16; g++)
            val += red[(half * 16 + g) * 264 + e];
        if (half == 1) red2[e] = val;
        __syncthreads();                   // (4)
        if (half == 0) {
            val += red2[e];
            int oii = e >> 6;
            int of  = e & 63;
            float r = val / dfin[oii];
            r = (r > 0.f) ? r : expm1f(r);
            out[(size_t)(r0 + oii) * Ff + of] = r;
        }
    }
}

// ---------------------------------------------------------------------------
extern "C" void kernel_launch(void* const* d_in, const int* in_sizes, int n_in,
                              void* d_out, int out_size) {
    const float* h   = (const float*)d_in[0];
    const int*   adj = (const int*)d_in[1];
    const float* W   = (const float*)d_in[2];
    const float* a   = (const float*)d_in[3];
    float* out = (float*)d_out;

    gat_k1<<<256, 256>>>(h, W, a);

    cudaLaunchConfig_t cfg = {};
    cfg.gridDim  = dim3(256, 1, 1);
    cfg.blockDim = dim3(512, 1, 1);
    cfg.dynamicSmemBytes = 0;
    cfg.stream = 0;
    cudaLaunchAttribute attrs[1];
    attrs[0].id = cudaLaunchAttributeProgrammaticStreamSerialization;
    attrs[0].val.programmaticStreamSerializationAllowed = 1;
    cfg.attrs = attrs;
    cfg.numAttrs = 1;
    cudaLaunchKernelEx(&cfg, gat_k2, adj, (float*)out);
}